// round 12
// baseline (speedup 1.0000x reference)
#include <cuda_runtime.h>
#include <cstdint>

#define N_NODES 2048
#define F_FEAT  64
#define C_OUT   8
#define GRID    512
#define JCHUNK  512
#define FSPLIT  4
#define FPER    (F_FEAT / FSPLIT)   // 16

// ---- persistent device state (no allocations allowed) ----
__device__ __align__(16) float g_part[FSPLIT * C_OUT * N_NODES];
__device__ float g_bpG[64];
__device__ float g_AG[65];
__device__ float g_BG[65];
__device__ unsigned g_bar = 0;        // monotone arrival counter (epochs)
__device__ unsigned g_bad_epoch = 0;  // epoch+1 if slice check failed

// fma-pipe reciprocal: magic init + 2 Newton iterations (rel err ~6e-6)
__device__ __forceinline__ float frcp_nr(float y) {
    float r = __int_as_float(0x7EF311C3 - __float_as_int(y));
    r = r * fmaf(-y, r, 2.0f);
    r = r * fmaf(-y, r, 2.0f);
    return r;
}

// ---------------------------------------------------------------------------
// One fused kernel, 512 blocks x 256 threads, all resident (4 blocks/SM).
// Phase A: per-feature NAM partials -> g_part; slice-scan of nd/nm sets
//          g_bad_epoch if (nm != 1) or !(nd >= top breakpoint) anywhere;
//          block 0 builds the PWL table of m(d).
// Spin barrier (epoch-based, replay-safe).
// Phase B: if clean: out = A64*(nd @ g) + B64*G  (pure FMA GEMM loop).
//          else: general per-element rcp + binary-search fallback.
// ---------------------------------------------------------------------------
__global__ void __launch_bounds__(256, 4) fused_kernel(
        const float* __restrict__ x,
        const float* __restrict__ nd,
        const float* __restrict__ nm,
        const float* __restrict__ W1,
        const float* __restrict__ b1,
        const float* __restrict__ W2,
        const float* __restrict__ b2,
        const float* __restrict__ Wm1,
        const float* __restrict__ bm1,
        const float* __restrict__ Wm2,
        const float* __restrict__ bm2,
        float* __restrict__ out) {
    __shared__ float gTs[C_OUT * JCHUNK];                 // 16KB
    __shared__ float s_t[64], s_bp[64], s_dA[64], s_dB[64];
    __shared__ float s_bias[C_OUT], sG[C_OUT];
    __shared__ float s_top;
    __shared__ unsigned s_epoch;

    int tid  = threadIdx.x;
    int lane = tid & 31;
    int warp = tid >> 5;
    int bx   = blockIdx.x;

    // epoch snapshot: g_bar in [512L, 512L+511] during this launch -> >>9 == L
    if (tid == 0) {
        unsigned c;
        asm volatile("ld.acquire.gpu.u32 %0, [%1];" : "=r"(c) : "l"(&g_bar));
        s_epoch = c >> 9;
    }

    // zero out (poisoned each replay); visible before barrier
    if (bx < 64) out[bx * 256 + tid] = 0.f;

    int fbase = (bx & 3) * FPER;

    // bias for this f-quarter
    if (tid < C_OUT) {
        float s = 0.f;
#pragma unroll
        for (int fi = 0; fi < FPER; fi++)
            s += b2[(fbase + fi) * C_OUT + tid];
        s_bias[tid] = s;
    }

    // breakpoints t_h = -bm1/Wm1 (inf if Wm1==0 -> forces general path)
    if (tid < 64) {
        float a = Wm1[tid], b = bm1[tid];
        s_t[tid] = (a != 0.f) ? (-b / a) : __int_as_float(0x7f800000);
    }
    __syncthreads();

    if (warp == 0) {
        float v = fmaxf(s_t[lane], s_t[lane + 32]);
#pragma unroll
        for (int o = 16; o; o >>= 1)
            v = fmaxf(v, __shfl_xor_sync(0xffffffffu, v, o));
        if (lane == 0) s_top = v;
    }
    __syncthreads();

    float top = s_top;
    unsigned epoch = s_epoch;

    // ---- slice scan: any (nm != 1) or !(nd >= top) => flag this epoch ----
    {
        const float4* nd4 = (const float4*)nd;
        const float4* nm4 = (const float4*)nm;
        int base4 = bx * 2048;   // 8192 floats per array per block
        int viol = 0;
#pragma unroll
        for (int k = 0; k < 8; k++) {
            float4 a = nd4[base4 + k * 256 + tid];
            float4 b = nm4[base4 + k * 256 + tid];
            viol |= (int)!(a.x >= top) | (int)!(a.y >= top) |
                    (int)!(a.z >= top) | (int)!(a.w >= top);
            viol |= (b.x != 1.f) | (b.y != 1.f) | (b.z != 1.f) | (b.w != 1.f);
        }
        if (__syncthreads_or(viol)) {
            if (tid == 0) atomicMax(&g_bad_epoch, epoch + 1);
        }
    }

    // ---- full PWL table (block 0, warp 0) for the fallback path ----
    if (bx == 0 && warp == 0) {
        float t[2], da[2], db[2], bA[2], bB[2];
#pragma unroll
        for (int e = 0; e < 2; e++) {
            int h = lane + e * 32;
            float a = Wm1[h], b = bm1[h], c = Wm2[h];
            float vda = 0.f, vdb = 0.f, vbA = 0.f, vbB = 0.f;
            if (a != 0.f) {
                float pa = a * c, pb = b * c;
                if (a > 0.f) { vda = pa;  vdb = pb; }
                else         { vda = -pa; vdb = -pb; vbA = pa; vbB = pb; }
            } else {
                if (b > 0.f) vbB = b * c;
            }
            t[e] = s_t[h]; da[e] = vda; db[e] = vdb; bA[e] = vbA; bB[e] = vbB;
        }
        int rk[2] = {0, 0};
        for (int k = 0; k < 64; k++) {
            float o = s_t[k];
            rk[0] += (o < t[0]) || (o == t[0] && k < lane);
            rk[1] += (o < t[1]) || (o == t[1] && k < lane + 32);
        }
        s_bp[rk[0]] = t[0]; s_dA[rk[0]] = da[0]; s_dB[rk[0]] = db[0];
        s_bp[rk[1]] = t[1]; s_dA[rk[1]] = da[1]; s_dB[rk[1]] = db[1];
        __syncwarp();

        float ra = bA[0] + bA[1], rb = bB[0] + bB[1];
#pragma unroll
        for (int o = 16; o; o >>= 1) {
            ra += __shfl_xor_sync(0xffffffffu, ra, o);
            rb += __shfl_xor_sync(0xffffffffu, rb, o);
        }
        float A0 = ra, B0 = rb + bm2[0];

        float a0 = s_dA[2 * lane], a1 = s_dA[2 * lane + 1];
        float b0 = s_dB[2 * lane], b1v = s_dB[2 * lane + 1];
        float sa = a0 + a1, sb = b0 + b1v;
        float ia = sa, ib = sb;
#pragma unroll
        for (int o = 1; o < 32; o <<= 1) {
            float ua = __shfl_up_sync(0xffffffffu, ia, o);
            float ub = __shfl_up_sync(0xffffffffu, ib, o);
            if (lane >= o) { ia += ua; ib += ub; }
        }
        float ea = ia - sa, eb = ib - sb;
        if (lane == 0) { g_AG[0] = A0; g_BG[0] = B0; }
        g_AG[2 * lane + 1] = A0 + ea + a0;
        g_BG[2 * lane + 1] = B0 + eb + b0;
        g_AG[2 * lane + 2] = A0 + ea + a0 + a1;
        g_BG[2 * lane + 2] = B0 + eb + b0 + b1v;
        g_bpG[2 * lane]     = s_bp[2 * lane];
        g_bpG[2 * lane + 1] = s_bp[2 * lane + 1];
    }

    // ---- phase A: NAM partials, warp = 2 rows x 16 features ----
    {
        int r0 = (bx >> 2) * 16 + warp * 2;
        int h0 = lane, h1 = lane + 32;

        float xr0 = x[r0 * F_FEAT + fbase + (lane & 15)];
        float xr1 = x[(r0 + 1) * F_FEAT + fbase + (lane & 15)];

        float acc0[C_OUT], acc1[C_OUT];
#pragma unroll
        for (int c = 0; c < C_OUT; c++) { acc0[c] = 0.f; acc1[c] = 0.f; }

#pragma unroll 4
        for (int fi = 0; fi < FPER; fi++) {
            int f = fbase + fi;
            float w1a = W1[f * 64 + h0], w1b = W1[f * 64 + h1];
            float c1a = b1[f * 64 + h0], c1b = b1[f * 64 + h1];
            const float4* wa = (const float4*)(W2 + (size_t)(f * 64 + h0) * 8);
            const float4* wb = (const float4*)(W2 + (size_t)(f * 64 + h1) * 8);
            float4 a0 = wa[0], a1 = wa[1];
            float4 b0v = wb[0], b1w = wb[1];

            float xv0 = __shfl_sync(0xffffffffu, xr0, fi);
            float xv1 = __shfl_sync(0xffffffffu, xr1, fi);

            float h0a = fmaxf(fmaf(xv0, w1a, c1a), 0.f);
            float h0b = fmaxf(fmaf(xv0, w1b, c1b), 0.f);
            float h1a = fmaxf(fmaf(xv1, w1a, c1a), 0.f);
            float h1b = fmaxf(fmaf(xv1, w1b, c1b), 0.f);

            acc0[0] = fmaf(h0a, a0.x, fmaf(h0b, b0v.x, acc0[0]));
            acc0[1] = fmaf(h0a, a0.y, fmaf(h0b, b0v.y, acc0[1]));
            acc0[2] = fmaf(h0a, a0.z, fmaf(h0b, b0v.z, acc0[2]));
            acc0[3] = fmaf(h0a, a0.w, fmaf(h0b, b0v.w, acc0[3]));
            acc0[4] = fmaf(h0a, a1.x, fmaf(h0b, b1w.x, acc0[4]));
            acc0[5] = fmaf(h0a, a1.y, fmaf(h0b, b1w.y, acc0[5]));
            acc0[6] = fmaf(h0a, a1.z, fmaf(h0b, b1w.z, acc0[6]));
            acc0[7] = fmaf(h0a, a1.w, fmaf(h0b, b1w.w, acc0[7]));

            acc1[0] = fmaf(h1a, a0.x, fmaf(h1b, b0v.x, acc1[0]));
            acc1[1] = fmaf(h1a, a0.y, fmaf(h1b, b0v.y, acc1[1]));
            acc1[2] = fmaf(h1a, a0.z, fmaf(h1b, b0v.z, acc1[2]));
            acc1[3] = fmaf(h1a, a0.w, fmaf(h1b, b0v.w, acc1[3]));
            acc1[4] = fmaf(h1a, a1.x, fmaf(h1b, b1w.x, acc1[4]));
            acc1[5] = fmaf(h1a, a1.y, fmaf(h1b, b1w.y, acc1[5]));
            acc1[6] = fmaf(h1a, a1.z, fmaf(h1b, b1w.z, acc1[6]));
            acc1[7] = fmaf(h1a, a1.w, fmaf(h1b, b1w.w, acc1[7]));
        }

#pragma unroll
        for (int c = 0; c < C_OUT; c++) {
#pragma unroll
            for (int o = 16; o; o >>= 1) {
                acc0[c] += __shfl_xor_sync(0xffffffffu, acc0[c], o);
                acc1[c] += __shfl_xor_sync(0xffffffffu, acc1[c], o);
            }
        }
        if (lane == 0) {
#pragma unroll
            for (int c = 0; c < C_OUT; c++) {
                g_part[((bx & 3) * C_OUT + c) * N_NODES + r0]     = acc0[c] + s_bias[c];
                g_part[((bx & 3) * C_OUT + c) * N_NODES + r0 + 1] = acc1[c] + s_bias[c];
            }
        }
    }

    // ---- device-wide barrier (epoch-based, replay-safe) ----
    __threadfence();
    __syncthreads();
    if (tid == 0) {
        atomicAdd(&g_bar, 1u);
        unsigned target = (epoch + 1u) << 9;
        unsigned cur;
        do {
            asm volatile("ld.acquire.gpu.u32 %0, [%1];" : "=r"(cur) : "l"(&g_bar));
            if (cur < target) __nanosleep(128);
        } while (cur < target);
    }
    __syncthreads();

    // ---- phase B ----
    unsigned badep;
    asm volatile("ld.global.cg.u32 %0, [%1];" : "=r"(badep) : "l"(&g_bad_epoch));
    bool slow = (badep >= epoch + 1u);

    int rg = bx & 127, jc = bx >> 7;
    int jbase = jc * JCHUNK;

    // stage gT chunk: sum of 4 f-quarter partials, float4
    {
        const float4* g4 = (const float4*)g_part;
        const int q = (C_OUT * N_NODES) >> 2;   // 4096 float4 per split
#pragma unroll
        for (int i = tid; i < (C_OUT * JCHUNK) >> 2; i += 256) {
            int c = i >> 7, j4 = i & 127;
            int off = c * (N_NODES >> 2) + (jbase >> 2) + j4;
            float4 p0 = g4[off], p1 = g4[q + off];
            float4 p2 = g4[2 * q + off], p3 = g4[3 * q + off];
            float4 s = make_float4(p0.x + p1.x + p2.x + p3.x,
                                   p0.y + p1.y + p2.y + p3.y,
                                   p0.z + p1.z + p2.z + p3.z,
                                   p0.w + p1.w + p2.w + p3.w);
            ((float4*)gTs)[i] = s;
        }
    }
    __syncthreads();

    // G_chunk[c] = sum_j gTs[c][j]  (warp c does column c)
    {
        float v = 0.f;
#pragma unroll
        for (int k = 0; k < 16; k++)
            v += gTs[warp * JCHUNK + k * 32 + lane];
#pragma unroll
        for (int o = 16; o; o >>= 1)
            v += __shfl_xor_sync(0xffffffffu, v, o);
        if (lane == 0) sG[warp] = v;
    }
    __syncthreads();

    int r0m = rg * 16 + warp * 2;
    int r1m = r0m + 1;
    const float* d0p = nd + (size_t)r0m * N_NODES + jbase;
    const float* d1p = nd + (size_t)r1m * N_NODES + jbase;

    float p0[C_OUT], p1[C_OUT];
#pragma unroll
    for (int c = 0; c < C_OUT; c++) { p0[c] = 0.f; p1[c] = 0.f; }

    if (!slow) {
        // FAST: pure GEMM accumulation P = nd @ g (branch-free)
        int jb = lane * 4;
        float4 f0 = *(const float4*)(d0p + jb);
        float4 f1 = *(const float4*)(d1p + jb);
#pragma unroll
        for (int it = 0; it < JCHUNK / 128; it++) {
            float4 c0 = f0, c1 = f1;
            int jn = jb + 128;
            if (it + 1 < JCHUNK / 128) {
                f0 = *(const float4*)(d0p + jn);
                f1 = *(const float4*)(d1p + jn);
            }
#pragma unroll
            for (int c = 0; c < C_OUT; c++) {
                float4 gv = *(const float4*)(gTs + c * JCHUNK + jb);
                p0[c] = fmaf(c0.x, gv.x, p0[c]);
                p0[c] = fmaf(c0.y, gv.y, p0[c]);
                p0[c] = fmaf(c0.z, gv.z, p0[c]);
                p0[c] = fmaf(c0.w, gv.w, p0[c]);
                p1[c] = fmaf(c1.x, gv.x, p1[c]);
                p1[c] = fmaf(c1.y, gv.y, p1[c]);
                p1[c] = fmaf(c1.z, gv.z, p1[c]);
                p1[c] = fmaf(c1.w, gv.w, p1[c]);
            }
            jb = jn;
        }

#pragma unroll
        for (int c = 0; c < C_OUT; c++) {
#pragma unroll
            for (int o = 16; o; o >>= 1) {
                p0[c] += __shfl_xor_sync(0xffffffffu, p0[c], o);
                p1[c] += __shfl_xor_sync(0xffffffffu, p1[c], o);
            }
        }
        float A64 = __ldcg(&g_AG[64]);
        float B64 = __ldcg(&g_BG[64]);
        if (lane == 0) {
#pragma unroll
            for (int c = 0; c < C_OUT; c++) {
                atomicAdd(&out[r0m * C_OUT + c], fmaf(A64, p0[c], B64 * sG[c]));
                atomicAdd(&out[r1m * C_OUT + c], fmaf(A64, p1[c], B64 * sG[c]));
            }
        }
    } else {
        // SLOW (general): per-element reciprocal + PWL binary search
        const float* n0p = nm + (size_t)r0m * N_NODES + jbase;
        const float* n1p = nm + (size_t)r1m * N_NODES + jbase;
        for (int jb = lane * 4; jb < JCHUNK; jb += 128) {
            float4 a0 = *(const float4*)(d0p + jb);
            float4 q0 = *(const float4*)(n0p + jb);
            float4 a1 = *(const float4*)(d1p + jb);
            float4 q1 = *(const float4*)(n1p + jb);
            float dv[8], m[8];
            dv[0] = a0.x * frcp_nr(q0.x); dv[1] = a0.y * frcp_nr(q0.y);
            dv[2] = a0.z * frcp_nr(q0.z); dv[3] = a0.w * frcp_nr(q0.w);
            dv[4] = a1.x * frcp_nr(q1.x); dv[5] = a1.y * frcp_nr(q1.y);
            dv[6] = a1.z * frcp_nr(q1.z); dv[7] = a1.w * frcp_nr(q1.w);
#pragma unroll
            for (int t = 0; t < 8; t++) {
                float d = dv[t];
                int k = 0;
#pragma unroll
                for (int s = 32; s >= 1; s >>= 1)
                    if (__ldg(&g_bpG[k + s - 1]) < d) k += s;
                m[t] = fmaf(__ldg(&g_AG[k]), d, __ldg(&g_BG[k]));
            }
#pragma unroll
            for (int c = 0; c < C_OUT; c++) {
                float4 gv = *(const float4*)(gTs + c * JCHUNK + jb);
                p0[c] = fmaf(m[0], gv.x, p0[c]);
                p0[c] = fmaf(m[1], gv.y, p0[c]);
                p0[c] = fmaf(m[2], gv.z, p0[c]);
                p0[c] = fmaf(m[3], gv.w, p0[c]);
                p1[c] = fmaf(m[4], gv.x, p1[c]);
                p1[c] = fmaf(m[5], gv.y, p1[c]);
                p1[c] = fmaf(m[6], gv.z, p1[c]);
                p1[c] = fmaf(m[7], gv.w, p1[c]);
            }
        }
#pragma unroll
        for (int c = 0; c < C_OUT; c++) {
#pragma unroll
            for (int o = 16; o; o >>= 1) {
                p0[c] += __shfl_xor_sync(0xffffffffu, p0[c], o);
                p1[c] += __shfl_xor_sync(0xffffffffu, p1[c], o);
            }
        }
        if (lane == 0) {
#pragma unroll
            for (int c = 0; c < C_OUT; c++) {
                atomicAdd(&out[r0m * C_OUT + c], p0[c]);
                atomicAdd(&out[r1m * C_OUT + c], p1[c]);
            }
        }
    }
}

// ---------------------------------------------------------------------------
extern "C" void kernel_launch(void* const* d_in, const int* in_sizes, int n_in,
                              void* d_out, int out_size) {
    const float* x   = (const float*)d_in[0];
    const float* nd  = (const float*)d_in[1];
    const float* nm  = (const float*)d_in[2];
    const float* W1  = (const float*)d_in[3];
    const float* b1  = (const float*)d_in[4];
    const float* W2  = (const float*)d_in[5];
    const float* b2  = (const float*)d_in[6];
    const float* Wm1 = (const float*)d_in[7];
    const float* bm1 = (const float*)d_in[8];
    const float* Wm2 = (const float*)d_in[9];
    const float* bm2 = (const float*)d_in[10];
    float* out = (float*)d_out;

    fused_kernel<<<GRID, 256>>>(x, nd, nm, W1, b1, W2, b2,
                                Wm1, bm1, Wm2, bm2, out);
}

// round 16
// speedup vs baseline: 1.7193x; 1.7193x over previous
#include <cuda_runtime.h>
#include <cstdint>

#define N_NODES 2048
#define F_FEAT  64
#define C_OUT   8
#define JCHUNK  512
#define NSPLIT  (N_NODES / JCHUNK)   // 4 j-chunks
#define FSPLIT  2
#define FPER    (F_FEAT / FSPLIT)    // 32 features per split

// partial g, per f-half: [s][c][j]  (pure writes -> replay-safe)
__device__ __align__(16) float g_part[FSPLIT * C_OUT * N_NODES];
// PWL table for m(d), built once by g_kernel block (0,0) warp 0
__device__ float g_bpG[64];
__device__ float g_AG[65];
__device__ float g_BG[65];

// fma-pipe reciprocal: magic init + 2 Newton iterations (rel err ~6e-6)
__device__ __forceinline__ float frcp_nr(float y) {
    float r = __int_as_float(0x7EF311C3 - __float_as_int(y));
    r = r * fmaf(-y, r, 2.0f);
    r = r * fmaf(-y, r, 2.0f);
    return r;
}

// ---------------------------------------------------------------------------
// g kernel: grid (256 rowgroups, 2 f-halves) x 128 threads (4 warps).
// Each warp: 2 rows x 32 features.
// g_part[s][c][j] = sum_{f in half s} sum_h relu(x*W1+b1)*W2 + sum_{f} b2
// Block (0,0) warp 0 additionally builds the PWL table for m(d).
// fs==0 blocks zero `out` (main accumulates atomically; replay-safe).
// ---------------------------------------------------------------------------
__global__ void __launch_bounds__(128) g_kernel(
        const float* __restrict__ x,
        const float* __restrict__ W1,
        const float* __restrict__ b1,
        const float* __restrict__ W2,
        const float* __restrict__ b2,
        const float* __restrict__ Wm1,
        const float* __restrict__ bm1,
        const float* __restrict__ Wm2,
        const float* __restrict__ bm2,
        float* __restrict__ out) {
    __shared__ float s_bias[C_OUT];
    __shared__ float w_t[64], s_bp[64], s_dA[64], s_dB[64];

    int tid  = threadIdx.x;
    int lane = tid & 31;
    int warp = tid >> 5;
    int by   = blockIdx.x;
    int fs   = blockIdx.y;
    int fbase = fs * FPER;

    // zero out (poisoned by harness; re-zeroed every graph replay)
    if (fs == 0 && tid < 64)
        out[by * 64 + tid] = 0.f;    // 256 blocks x 64 = 16384 = N*C

    if (tid < C_OUT) {
        float s = 0.f;
#pragma unroll
        for (int fi = 0; fi < FPER; fi++)
            s += b2[(fbase + fi) * C_OUT + tid];
        s_bias[tid] = s;
    }

    // ---- PWL table build (block (0,0), warp 0 only) ----
    if (by == 0 && fs == 0 && warp == 0) {
        float t[2], da[2], db[2], bA[2], bB[2];
#pragma unroll
        for (int e = 0; e < 2; e++) {
            int h = lane + e * 32;
            float a = Wm1[h], b = bm1[h], c = Wm2[h];
            float tt, vda = 0.f, vdb = 0.f, vbA = 0.f, vbB = 0.f;
            if (a != 0.f) {
                tt = -b / a;
                float pa = a * c, pb = b * c;
                if (a > 0.f) { vda = pa;  vdb = pb; }
                else         { vda = -pa; vdb = -pb; vbA = pa; vbB = pb; }
            } else {
                tt = __int_as_float(0x7f800000);
                if (b > 0.f) vbB = b * c;
            }
            t[e] = tt; da[e] = vda; db[e] = vdb; bA[e] = vbA; bB[e] = vbB;
        }
        w_t[lane] = t[0]; w_t[lane + 32] = t[1];
        __syncwarp();

        int rk[2] = {0, 0};
        for (int k = 0; k < 64; k++) {
            float o = w_t[k];
            rk[0] += (o < t[0]) || (o == t[0] && k < lane);
            rk[1] += (o < t[1]) || (o == t[1] && k < lane + 32);
        }
        s_bp[rk[0]] = t[0]; s_dA[rk[0]] = da[0]; s_dB[rk[0]] = db[0];
        s_bp[rk[1]] = t[1]; s_dA[rk[1]] = da[1]; s_dB[rk[1]] = db[1];
        __syncwarp();

        float ra = bA[0] + bA[1], rb = bB[0] + bB[1];
#pragma unroll
        for (int o = 16; o; o >>= 1) {
            ra += __shfl_xor_sync(0xffffffffu, ra, o);
            rb += __shfl_xor_sync(0xffffffffu, rb, o);
        }
        float A0 = ra, B0 = rb + bm2[0];

        float a0 = s_dA[2 * lane], a1 = s_dA[2 * lane + 1];
        float b0 = s_dB[2 * lane], b1v = s_dB[2 * lane + 1];
        float sa = a0 + a1, sb = b0 + b1v;
        float ia = sa, ib = sb;
#pragma unroll
        for (int o = 1; o < 32; o <<= 1) {
            float ua = __shfl_up_sync(0xffffffffu, ia, o);
            float ub = __shfl_up_sync(0xffffffffu, ib, o);
            if (lane >= o) { ia += ua; ib += ub; }
        }
        float ea = ia - sa, eb = ib - sb;   // exclusive prefix
        if (lane == 0) { g_AG[0] = A0; g_BG[0] = B0; }
        g_AG[2 * lane + 1] = A0 + ea + a0;
        g_BG[2 * lane + 1] = B0 + eb + b0;
        g_AG[2 * lane + 2] = A0 + ea + a0 + a1;
        g_BG[2 * lane + 2] = B0 + eb + b0 + b1v;
        g_bpG[2 * lane]     = s_bp[2 * lane];
        g_bpG[2 * lane + 1] = s_bp[2 * lane + 1];
    }

    // ---- per-feature NAM accumulation: 2 rows x 32 features per warp ----
    int r0 = by * 8 + warp * 2;
    int h0 = lane, h1 = lane + 32;

    float xr0 = x[r0 * F_FEAT + fbase + lane];
    float xr1 = x[(r0 + 1) * F_FEAT + fbase + lane];

    float acc0[C_OUT], acc1[C_OUT];
#pragma unroll
    for (int c = 0; c < C_OUT; c++) { acc0[c] = 0.f; acc1[c] = 0.f; }

#pragma unroll 4
    for (int fi = 0; fi < FPER; fi++) {
        int f = fbase + fi;
        float w1a = W1[f * 64 + h0], w1b = W1[f * 64 + h1];
        float c1a = b1[f * 64 + h0], c1b = b1[f * 64 + h1];
        const float4* wa = (const float4*)(W2 + (size_t)(f * 64 + h0) * 8);
        const float4* wb = (const float4*)(W2 + (size_t)(f * 64 + h1) * 8);
        float4 a0 = wa[0], a1 = wa[1];
        float4 b0v = wb[0], b1w = wb[1];

        float xv0 = __shfl_sync(0xffffffffu, xr0, fi);
        float xv1 = __shfl_sync(0xffffffffu, xr1, fi);

        float h0a = fmaxf(fmaf(xv0, w1a, c1a), 0.f);
        float h0b = fmaxf(fmaf(xv0, w1b, c1b), 0.f);
        float h1a = fmaxf(fmaf(xv1, w1a, c1a), 0.f);
        float h1b = fmaxf(fmaf(xv1, w1b, c1b), 0.f);

        acc0[0] = fmaf(h0a, a0.x, fmaf(h0b, b0v.x, acc0[0]));
        acc0[1] = fmaf(h0a, a0.y, fmaf(h0b, b0v.y, acc0[1]));
        acc0[2] = fmaf(h0a, a0.z, fmaf(h0b, b0v.z, acc0[2]));
        acc0[3] = fmaf(h0a, a0.w, fmaf(h0b, b0v.w, acc0[3]));
        acc0[4] = fmaf(h0a, a1.x, fmaf(h0b, b1w.x, acc0[4]));
        acc0[5] = fmaf(h0a, a1.y, fmaf(h0b, b1w.y, acc0[5]));
        acc0[6] = fmaf(h0a, a1.z, fmaf(h0b, b1w.z, acc0[6]));
        acc0[7] = fmaf(h0a, a1.w, fmaf(h0b, b1w.w, acc0[7]));

        acc1[0] = fmaf(h1a, a0.x, fmaf(h1b, b0v.x, acc1[0]));
        acc1[1] = fmaf(h1a, a0.y, fmaf(h1b, b0v.y, acc1[1]));
        acc1[2] = fmaf(h1a, a0.z, fmaf(h1b, b0v.z, acc1[2]));
        acc1[3] = fmaf(h1a, a0.w, fmaf(h1b, b0v.w, acc1[3]));
        acc1[4] = fmaf(h1a, a1.x, fmaf(h1b, b1w.x, acc1[4]));
        acc1[5] = fmaf(h1a, a1.y, fmaf(h1b, b1w.y, acc1[5]));
        acc1[6] = fmaf(h1a, a1.z, fmaf(h1b, b1w.z, acc1[6]));
        acc1[7] = fmaf(h1a, a1.w, fmaf(h1b, b1w.w, acc1[7]));
    }

#pragma unroll
    for (int c = 0; c < C_OUT; c++) {
#pragma unroll
        for (int o = 16; o; o >>= 1) {
            acc0[c] += __shfl_xor_sync(0xffffffffu, acc0[c], o);
            acc1[c] += __shfl_xor_sync(0xffffffffu, acc1[c], o);
        }
    }

    __syncthreads();   // s_bias ready
    if (lane == 0) {
#pragma unroll
        for (int c = 0; c < C_OUT; c++) {
            g_part[(fs * C_OUT + c) * N_NODES + r0]     = acc0[c] + s_bias[c];
            g_part[(fs * C_OUT + c) * N_NODES + r0 + 1] = acc1[c] + s_bias[c];
        }
    }
}

// ---------------------------------------------------------------------------
// Main kernel: out[i,c] += sum_{j in chunk} m(nd[i,j]/nm[i,j]) * g[j,c]
// Grid (128 rowgroups x 4 j-chunks) = 512 blocks, 4/SM (32 warps/SM).
//
// Each block first SCANS ITS OWN 16x512 tile of nd/nm (high-MLP float4
// loads): clean iff every nm == 1 and every nd >= top-breakpoint. The
// result is folded block-uniform via __syncthreads_or -- ONE branch for
// the whole block, no per-iteration votes, no barriers, no global flags.
//
// Clean (the common case): m(d) = A64*nd + B64 exactly, so
//   out_chunk = A64 * (nd_tile @ g_chunk) + B64 * G_chunk
// -> a pure branch-free FMA GEMM loop; nd is L1-resident from the scan
// (32KB/tile x 4 blocks = 128KB < 228KB L1). nm never touches the loop.
// Dirty: fully general per-element rcp + PWL binary search fallback.
// ---------------------------------------------------------------------------
__global__ void __launch_bounds__(256, 4) main_kernel(
        const float* __restrict__ nd,
        const float* __restrict__ nm,
        float* __restrict__ out) {
    __shared__ float gTs[C_OUT * JCHUNK];   // 16KB
    __shared__ float sG[C_OUT];

    int tid = threadIdx.x;
    int warp = tid >> 5, lane = tid & 31;
    int jbase = blockIdx.y * JCHUNK;

    // stage gT chunk: float4 loads, sum of the 2 f-half partials
    {
        const float4* g4 = (const float4*)g_part;
        const int half4 = (C_OUT * N_NODES) >> 2;
#pragma unroll
        for (int i = tid; i < (C_OUT * JCHUNK) >> 2; i += 256) {
            int c = i >> 7, j4 = i & 127;            // 128 float4 per c-row
            int off = ((c * N_NODES + jbase) >> 2) + j4;
            float4 a = g4[off];
            float4 b = g4[half4 + off];
            ((float4*)gTs)[i] = make_float4(a.x + b.x, a.y + b.y,
                                            a.z + b.z, a.w + b.w);
        }
    }

    float top = __ldg(&g_bpG[63]);
    float A64 = __ldg(&g_AG[64]);
    float B64 = __ldg(&g_BG[64]);

    int r0m = blockIdx.x * 16 + warp * 2;
    int r1m = r0m + 1;
    const float* d0p = nd + (size_t)r0m * N_NODES + jbase;
    const float* n0p = nm + (size_t)r0m * N_NODES + jbase;
    const float* d1p = nd + (size_t)r1m * N_NODES + jbase;
    const float* n1p = nm + (size_t)r1m * N_NODES + jbase;

    // ---- tile scan: 16 independent float4 loads per thread (high MLP) ----
    int viol = 0;
#pragma unroll
    for (int it = 0; it < 4; it++) {
        int jb = it * 128 + lane * 4;
        float4 a0 = *(const float4*)(d0p + jb);
        float4 q0 = *(const float4*)(n0p + jb);
        float4 a1 = *(const float4*)(d1p + jb);
        float4 q1 = *(const float4*)(n1p + jb);
        viol |= (int)!(a0.x >= top) | (int)!(a0.y >= top) |
                (int)!(a0.z >= top) | (int)!(a0.w >= top) |
                (int)!(a1.x >= top) | (int)!(a1.y >= top) |
                (int)!(a1.z >= top) | (int)!(a1.w >= top);
        viol |= (q0.x != 1.f) | (q0.y != 1.f) | (q0.z != 1.f) | (q0.w != 1.f) |
                (q1.x != 1.f) | (q1.y != 1.f) | (q1.z != 1.f) | (q1.w != 1.f);
    }
    int slow = __syncthreads_or(viol);   // also orders gTs writes

    // G_chunk[c] = sum_j gTs[c][j]  (warp c sums column c)
    if (warp < C_OUT) {
        float v = 0.f;
#pragma unroll
        for (int k = 0; k < 16; k++)
            v += gTs[warp * JCHUNK + k * 32 + lane];
#pragma unroll
        for (int o = 16; o; o >>= 1)
            v += __shfl_xor_sync(0xffffffffu, v, o);
        if (lane == 0) sG[warp] = v;
    }
    __syncthreads();

    float p0[C_OUT], p1[C_OUT];
#pragma unroll
    for (int c = 0; c < C_OUT; c++) { p0[c] = 0.f; p1[c] = 0.f; }

    if (!slow) {
        // FAST: pure GEMM P = nd_tile @ g_chunk (branch-free, nd L1-hot)
        int jb = lane * 4;
        float4 f0 = *(const float4*)(d0p + jb);
        float4 f1 = *(const float4*)(d1p + jb);
#pragma unroll
        for (int it = 0; it < JCHUNK / 128; it++) {
            float4 c0 = f0, c1 = f1;
            int jn = jb + 128;
            if (it + 1 < JCHUNK / 128) {
                f0 = *(const float4*)(d0p + jn);
                f1 = *(const float4*)(d1p + jn);
            }
#pragma unroll
            for (int c = 0; c < C_OUT; c++) {
                float4 gv = *(const float4*)(gTs + c * JCHUNK + jb);
                p0[c] = fmaf(c0.x, gv.x, p0[c]);
                p0[c] = fmaf(c0.y, gv.y, p0[c]);
                p0[c] = fmaf(c0.z, gv.z, p0[c]);
                p0[c] = fmaf(c0.w, gv.w, p0[c]);
                p1[c] = fmaf(c1.x, gv.x, p1[c]);
                p1[c] = fmaf(c1.y, gv.y, p1[c]);
                p1[c] = fmaf(c1.z, gv.z, p1[c]);
                p1[c] = fmaf(c1.w, gv.w, p1[c]);
            }
            jb = jn;
        }

#pragma unroll
        for (int c = 0; c < C_OUT; c++) {
#pragma unroll
            for (int o = 16; o; o >>= 1) {
                p0[c] += __shfl_xor_sync(0xffffffffu, p0[c], o);
                p1[c] += __shfl_xor_sync(0xffffffffu, p1[c], o);
            }
        }
        if (lane == 0) {
#pragma unroll
            for (int c = 0; c < C_OUT; c++) {
                atomicAdd(&out[r0m * C_OUT + c], fmaf(A64, p0[c], B64 * sG[c]));
                atomicAdd(&out[r1m * C_OUT + c], fmaf(A64, p1[c], B64 * sG[c]));
            }
        }
    } else {
        // SLOW (fully general): per-element reciprocal + PWL binary search
        for (int jb = lane * 4; jb < JCHUNK; jb += 128) {
            float4 a0 = *(const float4*)(d0p + jb);
            float4 q0 = *(const float4*)(n0p + jb);
            float4 a1 = *(const float4*)(d1p + jb);
            float4 q1 = *(const float4*)(n1p + jb);
            float dv[8], m[8];
            dv[0] = a0.x * frcp_nr(q0.x); dv[1] = a0.y * frcp_nr(q0.y);
            dv[2] = a0.z * frcp_nr(q0.z); dv[3] = a0.w * frcp_nr(q0.w);
            dv[4] = a1.x * frcp_nr(q1.x); dv[5] = a1.y * frcp_nr(q1.y);
            dv[6] = a1.z * frcp_nr(q1.z); dv[7] = a1.w * frcp_nr(q1.w);
#pragma unroll
            for (int t = 0; t < 8; t++) {
                float d = dv[t];
                int k = 0;
#pragma unroll
                for (int s = 32; s >= 1; s >>= 1)
                    if (__ldg(&g_bpG[k + s - 1]) < d) k += s;
                m[t] = fmaf(__ldg(&g_AG[k]), d, __ldg(&g_BG[k]));
            }
#pragma unroll
            for (int c = 0; c < C_OUT; c++) {
                float4 gv = *(const float4*)(gTs + c * JCHUNK + jb);
                p0[c] = fmaf(m[0], gv.x, p0[c]);
                p0[c] = fmaf(m[1], gv.y, p0[c]);
                p0[c] = fmaf(m[2], gv.z, p0[c]);
                p0[c] = fmaf(m[3], gv.w, p0[c]);
                p1[c] = fmaf(m[4], gv.x, p1[c]);
                p1[c] = fmaf(m[5], gv.y, p1[c]);
                p1[c] = fmaf(m[6], gv.z, p1[c]);
                p1[c] = fmaf(m[7], gv.w, p1[c]);
            }
        }
#pragma unroll
        for (int c = 0; c < C_OUT; c++) {
#pragma unroll
            for (int o = 16; o; o >>= 1) {
                p0[c] += __shfl_xor_sync(0xffffffffu, p0[c], o);
                p1[c] += __shfl_xor_sync(0xffffffffu, p1[c], o);
            }
        }
        if (lane == 0) {
#pragma unroll
            for (int c = 0; c < C_OUT; c++) {
                atomicAdd(&out[r0m * C_OUT + c], p0[c]);
                atomicAdd(&out[r1m * C_OUT + c], p1[c]);
            }
        }
    }
}

// ---------------------------------------------------------------------------
extern "C" void kernel_launch(void* const* d_in, const int* in_sizes, int n_in,
                              void* d_out, int out_size) {
    const float* x   = (const float*)d_in[0];
    const float* nd  = (const float*)d_in[1];
    const float* nm  = (const float*)d_in[2];
    const float* W1  = (const float*)d_in[3];
    const float* b1  = (const float*)d_in[4];
    const float* W2  = (const float*)d_in[5];
    const float* b2  = (const float*)d_in[6];
    const float* Wm1 = (const float*)d_in[7];
    const float* bm1 = (const float*)d_in[8];
    const float* Wm2 = (const float*)d_in[9];
    const float* bm2 = (const float*)d_in[10];
    float* out = (float*)d_out;

    dim3 ggrid(N_NODES / 8, FSPLIT);
    g_kernel<<<ggrid, 128>>>(x, W1, b1, W2, b2, Wm1, bm1, Wm2, bm2, out);

    dim3 mgrid(N_NODES / 16, NSPLIT);
    main_kernel<<<mgrid, 256>>>(nd, nm, out);
}

// round 17
// speedup vs baseline: 2.0513x; 1.1931x over previous
#include <cuda_runtime.h>
#include <cstdint>

#define N_NODES 2048
#define F_FEAT  64
#define C_OUT   8
#define JCHUNK  512
#define NSPLIT  (N_NODES / JCHUNK)   // 4

// final g (bias included), [c][j] layout
__device__ __align__(16) float g_g[C_OUT * N_NODES];
// PWL table for m(d)
__device__ float g_bpG[64];
__device__ float g_AG[65];
__device__ float g_BG[65];

// fma-pipe reciprocal (rel err ~6e-6), used only on the cold path
__device__ __forceinline__ float frcp_nr(float y) {
    float r = __int_as_float(0x7EF311C3 - __float_as_int(y));
    r = r * fmaf(-y, r, 2.0f);
    r = r * fmaf(-y, r, 2.0f);
    return r;
}

// ---------------------------------------------------------------------------
// g kernel: 128 blocks x 256 threads, 16 rows/block (warp = 2 rows).
//
// Fast path (b1 == 0, block-checked): the H dimension collapses:
//   sum_h relu(x*W1[f,h]) * W2[f,h,c] = x * (x>0 ? P[f,c] : M[f,c])
//   P[f,c] = sum_{h:W1>0} W1*W2,  M[f,c] = sum_{h:W1<0} W1*W2
// -> g[j,c] = sum_f x[j,f]*PM[sel][f][c] + sum_f b2[f,c]   (~1M FMA total)
// Fallback (b1 != 0): full relu-MLP math per (row, f, h).
//
// Block 0 warp 0 builds the PWL table of m(d). All blocks zero their out
// slice (out poisoned every replay; main accumulates atomically).
// ---------------------------------------------------------------------------
__global__ void __launch_bounds__(256) g_kernel(
        const float* __restrict__ x,
        const float* __restrict__ W1,
        const float* __restrict__ b1,
        const float* __restrict__ W2,
        const float* __restrict__ b2,
        const float* __restrict__ Wm1,
        const float* __restrict__ bm1,
        const float* __restrict__ Wm2,
        const float* __restrict__ bm2,
        float* __restrict__ out) {
    __shared__ float sPM[2 * 64 * C_OUT];        // 4KB: [sel][f][c]
    __shared__ float s_bt[64][C_OUT];            // 2KB bias tree
    __shared__ float w_t[64], s_bp[64], s_dA[64], s_dB[64];

    int tid  = threadIdx.x;
    int lane = tid & 31;
    int warp = tid >> 5;
    int bx   = blockIdx.x;

    // zero out slice: 128 blocks x 128 = 16384 = N*C
    if (tid < 128) out[bx * 128 + tid] = 0.f;

    // ---- bias tree: s_bt[0][c] = sum_f b2[f,c] ----
    if (tid < 64) {
        float4 v0 = *(const float4*)(b2 + tid * 8);
        float4 v1 = *(const float4*)(b2 + tid * 8 + 4);
        s_bt[tid][0] = v0.x; s_bt[tid][1] = v0.y;
        s_bt[tid][2] = v0.z; s_bt[tid][3] = v0.w;
        s_bt[tid][4] = v1.x; s_bt[tid][5] = v1.y;
        s_bt[tid][6] = v1.z; s_bt[tid][7] = v1.w;
    }

    // ---- b1 == 0 check (whole 64x64 table, float4) ----
    int violb1 = 0;
    {
        const float4* b14 = (const float4*)b1;
#pragma unroll
        for (int k = 0; k < 4; k++) {
            float4 v = b14[k * 256 + tid];
            violb1 |= (v.x != 0.f) | (v.y != 0.f) | (v.z != 0.f) | (v.w != 0.f);
        }
    }

    // ---- PWL table build (block 0, warp 0) ----
    if (bx == 0 && warp == 0) {
        float t[2], da[2], db[2], bA[2], bB[2];
#pragma unroll
        for (int e = 0; e < 2; e++) {
            int h = lane + e * 32;
            float a = Wm1[h], b = bm1[h], c = Wm2[h];
            float tt, vda = 0.f, vdb = 0.f, vbA = 0.f, vbB = 0.f;
            if (a != 0.f) {
                tt = -b / a;
                float pa = a * c, pb = b * c;
                if (a > 0.f) { vda = pa;  vdb = pb; }
                else         { vda = -pa; vdb = -pb; vbA = pa; vbB = pb; }
            } else {
                tt = __int_as_float(0x7f800000);
                if (b > 0.f) vbB = b * c;
            }
            t[e] = tt; da[e] = vda; db[e] = vdb; bA[e] = vbA; bB[e] = vbB;
        }
        w_t[lane] = t[0]; w_t[lane + 32] = t[1];
        __syncwarp();

        int rk[2] = {0, 0};
        for (int k = 0; k < 64; k++) {
            float o = w_t[k];
            rk[0] += (o < t[0]) || (o == t[0] && k < lane);
            rk[1] += (o < t[1]) || (o == t[1] && k < lane + 32);
        }
        s_bp[rk[0]] = t[0]; s_dA[rk[0]] = da[0]; s_dB[rk[0]] = db[0];
        s_bp[rk[1]] = t[1]; s_dA[rk[1]] = da[1]; s_dB[rk[1]] = db[1];
        __syncwarp();

        float ra = bA[0] + bA[1], rb = bB[0] + bB[1];
#pragma unroll
        for (int o = 16; o; o >>= 1) {
            ra += __shfl_xor_sync(0xffffffffu, ra, o);
            rb += __shfl_xor_sync(0xffffffffu, rb, o);
        }
        float A0 = ra, B0 = rb + bm2[0];

        float a0 = s_dA[2 * lane], a1 = s_dA[2 * lane + 1];
        float b0 = s_dB[2 * lane], b1v = s_dB[2 * lane + 1];
        float sa = a0 + a1, sb = b0 + b1v;
        float ia = sa, ib = sb;
#pragma unroll
        for (int o = 1; o < 32; o <<= 1) {
            float ua = __shfl_up_sync(0xffffffffu, ia, o);
            float ub = __shfl_up_sync(0xffffffffu, ib, o);
            if (lane >= o) { ia += ua; ib += ub; }
        }
        float ea = ia - sa, eb = ib - sb;
        if (lane == 0) { g_AG[0] = A0; g_BG[0] = B0; }
        g_AG[2 * lane + 1] = A0 + ea + a0;
        g_BG[2 * lane + 1] = B0 + eb + b0;
        g_AG[2 * lane + 2] = A0 + ea + a0 + a1;
        g_BG[2 * lane + 2] = B0 + eb + b0 + b1v;
        g_bpG[2 * lane]     = s_bp[2 * lane];
        g_bpG[2 * lane + 1] = s_bp[2 * lane + 1];
    }

    // ---- build P/M tables: thread -> (f = tid>>2, c-pair = (tid&3)*2) ----
    {
        int f = tid >> 2, c = (tid & 3) * 2;
        float p0 = 0.f, p1 = 0.f, m0 = 0.f, m1 = 0.f;
#pragma unroll 8
        for (int h = 0; h < 64; h++) {
            float w = __ldg(&W1[f * 64 + h]);
            float2 w2 = __ldg((const float2*)&W2[(size_t)f * 512 + h * 8 + c]);
            float a = w * w2.x, b = w * w2.y;
            bool pos = (w > 0.f);
            p0 += pos ? a : 0.f;  m0 += pos ? 0.f : a;
            p1 += pos ? b : 0.f;  m1 += pos ? 0.f : b;
        }
        sPM[f * 8 + c]       = p0;
        sPM[f * 8 + c + 1]   = p1;
        sPM[512 + f * 8 + c]     = m0;
        sPM[512 + f * 8 + c + 1] = m1;
    }

    // bias tree reduce
    __syncthreads();
#pragma unroll
    for (int off = 32; off >= 1; off >>= 1) {
        if (tid < off)
#pragma unroll
            for (int c = 0; c < C_OUT; c++)
                s_bt[tid][c] += s_bt[tid + off][c];
        __syncthreads();
    }
    int slowg = __syncthreads_or(violb1);

    int r0 = bx * 16 + warp * 2;

    if (!slowg) {
        // ---- FAST: g[row,c] = sum_f x*PM[sel][f][:] ----
#pragma unroll
        for (int r = 0; r < 2; r++) {
            int row = r0 + r;
            float xv0 = x[row * F_FEAT + lane];
            float xv1 = x[row * F_FEAT + lane + 32];
            const float* pm0 = sPM + (xv0 > 0.f ? 0 : 512) + lane * 8;
            const float* pm1 = sPM + (xv1 > 0.f ? 0 : 512) + (lane + 32) * 8;

            float4 u0 = *(const float4*)(pm0);
            float4 u1 = *(const float4*)(pm0 + 4);
            float4 v0 = *(const float4*)(pm1);
            float4 v1 = *(const float4*)(pm1 + 4);

            float acc[C_OUT];
            acc[0] = fmaf(xv0, u0.x, xv1 * v0.x);
            acc[1] = fmaf(xv0, u0.y, xv1 * v0.y);
            acc[2] = fmaf(xv0, u0.z, xv1 * v0.z);
            acc[3] = fmaf(xv0, u0.w, xv1 * v0.w);
            acc[4] = fmaf(xv0, u1.x, xv1 * v1.x);
            acc[5] = fmaf(xv0, u1.y, xv1 * v1.y);
            acc[6] = fmaf(xv0, u1.z, xv1 * v1.z);
            acc[7] = fmaf(xv0, u1.w, xv1 * v1.w);

#pragma unroll
            for (int c = 0; c < C_OUT; c++)
#pragma unroll
                for (int o = 16; o; o >>= 1)
                    acc[c] += __shfl_xor_sync(0xffffffffu, acc[c], o);

            if (lane == 0)
#pragma unroll
                for (int c = 0; c < C_OUT; c++)
                    g_g[c * N_NODES + row] = acc[c] + s_bt[0][c];
        }
    } else {
        // ---- SLOW (general b1): full relu-MLP, 2 rows x 64 f per warp ----
        float xr0a = x[r0 * F_FEAT + lane];
        float xr0b = x[r0 * F_FEAT + lane + 32];
        float xr1a = x[(r0 + 1) * F_FEAT + lane];
        float xr1b = x[(r0 + 1) * F_FEAT + lane + 32];

        float acc0[C_OUT], acc1[C_OUT];
#pragma unroll
        for (int c = 0; c < C_OUT; c++) { acc0[c] = 0.f; acc1[c] = 0.f; }

        int h0 = lane, h1 = lane + 32;
        for (int f = 0; f < F_FEAT; f++) {
            float w1a = W1[f * 64 + h0], w1b = W1[f * 64 + h1];
            float c1a = b1[f * 64 + h0], c1b = b1[f * 64 + h1];
            const float4* wa = (const float4*)(W2 + (size_t)(f * 64 + h0) * 8);
            const float4* wb = (const float4*)(W2 + (size_t)(f * 64 + h1) * 8);
            float4 a0 = wa[0], a1 = wa[1];
            float4 b0v = wb[0], b1w = wb[1];

            float xv0 = __shfl_sync(0xffffffffu, (f < 32) ? xr0a : xr0b, f & 31);
            float xv1 = __shfl_sync(0xffffffffu, (f < 32) ? xr1a : xr1b, f & 31);

            float h0a = fmaxf(fmaf(xv0, w1a, c1a), 0.f);
            float h0b = fmaxf(fmaf(xv0, w1b, c1b), 0.f);
            float h1a = fmaxf(fmaf(xv1, w1a, c1a), 0.f);
            float h1b = fmaxf(fmaf(xv1, w1b, c1b), 0.f);

            acc0[0] = fmaf(h0a, a0.x, fmaf(h0b, b0v.x, acc0[0]));
            acc0[1] = fmaf(h0a, a0.y, fmaf(h0b, b0v.y, acc0[1]));
            acc0[2] = fmaf(h0a, a0.z, fmaf(h0b, b0v.z, acc0[2]));
            acc0[3] = fmaf(h0a, a0.w, fmaf(h0b, b0v.w, acc0[3]));
            acc0[4] = fmaf(h0a, a1.x, fmaf(h0b, b1w.x, acc0[4]));
            acc0[5] = fmaf(h0a, a1.y, fmaf(h0b, b1w.y, acc0[5]));
            acc0[6] = fmaf(h0a, a1.z, fmaf(h0b, b1w.z, acc0[6]));
            acc0[7] = fmaf(h0a, a1.w, fmaf(h0b, b1w.w, acc0[7]));

            acc1[0] = fmaf(h1a, a0.x, fmaf(h1b, b0v.x, acc1[0]));
            acc1[1] = fmaf(h1a, a0.y, fmaf(h1b, b0v.y, acc1[1]));
            acc1[2] = fmaf(h1a, a0.z, fmaf(h1b, b0v.z, acc1[2]));
            acc1[3] = fmaf(h1a, a0.w, fmaf(h1b, b0v.w, acc1[3]));
            acc1[4] = fmaf(h1a, a1.x, fmaf(h1b, b1w.x, acc1[4]));
            acc1[5] = fmaf(h1a, a1.y, fmaf(h1b, b1w.y, acc1[5]));
            acc1[6] = fmaf(h1a, a1.z, fmaf(h1b, b1w.z, acc1[6]));
            acc1[7] = fmaf(h1a, a1.w, fmaf(h1b, b1w.w, acc1[7]));
        }

#pragma unroll
        for (int c = 0; c < C_OUT; c++) {
#pragma unroll
            for (int o = 16; o; o >>= 1) {
                acc0[c] += __shfl_xor_sync(0xffffffffu, acc0[c], o);
                acc1[c] += __shfl_xor_sync(0xffffffffu, acc1[c], o);
            }
        }
        if (lane == 0) {
#pragma unroll
            for (int c = 0; c < C_OUT; c++) {
                g_g[c * N_NODES + r0]     = acc0[c] + s_bt[0][c];
                g_g[c * N_NODES + r0 + 1] = acc1[c] + s_bt[0][c];
            }
        }
    }
}

// ---------------------------------------------------------------------------
// Main kernel: speculative single-pass GEMM with in-loop validity tracking.
// Grid (128 x 4) = 512 blocks, 4/SM. Loop body is branch-free: 4 LDG.128,
// 16 compares folded into a viol register, 8 LDS.128, 64 FMA. After the
// loop ONE __syncthreads_or decides: clean -> scale+atomicAdd (common);
// dirty -> recompute this tile from L2 with the general rcp+PWL path.
// ---------------------------------------------------------------------------
__global__ void __launch_bounds__(256, 4) main_kernel(
        const float* __restrict__ nd,
        const float* __restrict__ nm,
        float* __restrict__ out) {
    __shared__ float gTs[C_OUT * JCHUNK];   // 16KB
    __shared__ float sG[C_OUT];

    int tid = threadIdx.x;
    int warp = tid >> 5, lane = tid & 31;
    int jbase = blockIdx.y * JCHUNK;

    // stage g chunk (single final array now)
    {
        const float4* g4 = (const float4*)g_g;
#pragma unroll
        for (int i = tid; i < (C_OUT * JCHUNK) >> 2; i += 256) {
            int c = i >> 7, j4 = i & 127;
            ((float4*)gTs)[i] = g4[((c * N_NODES + jbase) >> 2) + j4];
        }
    }
    float top = __ldg(&g_bpG[63]);
    float A64 = __ldg(&g_AG[64]);
    float B64 = __ldg(&g_BG[64]);
    __syncthreads();

    // G_chunk[c] = sum_j gTs[c][j]
    if (warp < C_OUT) {
        float v = 0.f;
#pragma unroll
        for (int k = 0; k < 16; k++)
            v += gTs[warp * JCHUNK + k * 32 + lane];
#pragma unroll
        for (int o = 16; o; o >>= 1)
            v += __shfl_xor_sync(0xffffffffu, v, o);
        if (lane == 0) sG[warp] = v;
    }
    __syncthreads();

    int r0m = blockIdx.x * 16 + warp * 2;
    int r1m = r0m + 1;
    const float* d0p = nd + (size_t)r0m * N_NODES + jbase;
    const float* n0p = nm + (size_t)r0m * N_NODES + jbase;
    const float* d1p = nd + (size_t)r1m * N_NODES + jbase;
    const float* n1p = nm + (size_t)r1m * N_NODES + jbase;

    float p0[C_OUT], p1[C_OUT];
#pragma unroll
    for (int c = 0; c < C_OUT; c++) { p0[c] = 0.f; p1[c] = 0.f; }

    int viol = 0;
    int jb = lane * 4;
    float4 a0 = __ldcs((const float4*)(d0p + jb));
    float4 a1 = __ldcs((const float4*)(d1p + jb));
    float4 q0 = __ldcs((const float4*)(n0p + jb));
    float4 q1 = __ldcs((const float4*)(n1p + jb));

#pragma unroll
    for (int it = 0; it < JCHUNK / 128; it++) {
        float4 c0 = a0, c1 = a1, r0q = q0, r1q = q1;
        int jn = jb + 128;
        if (it + 1 < JCHUNK / 128) {
            a0 = __ldcs((const float4*)(d0p + jn));
            a1 = __ldcs((const float4*)(d1p + jn));
            q0 = __ldcs((const float4*)(n0p + jn));
            q1 = __ldcs((const float4*)(n1p + jn));
        }

        // validity tracking (no branches)
        viol |= (r0q.x != 1.f) | (r0q.y != 1.f) | (r0q.z != 1.f) | (r0q.w != 1.f)
              | (r1q.x != 1.f) | (r1q.y != 1.f) | (r1q.z != 1.f) | (r1q.w != 1.f);
        viol |= (int)!(c0.x >= top) | (int)!(c0.y >= top)
              | (int)!(c0.z >= top) | (int)!(c0.w >= top)
              | (int)!(c1.x >= top) | (int)!(c1.y >= top)
              | (int)!(c1.z >= top) | (int)!(c1.w >= top);

#pragma unroll
        for (int c = 0; c < C_OUT; c++) {
            float4 gv = *(const float4*)(gTs + c * JCHUNK + jb);
            p0[c] = fmaf(c0.x, gv.x, p0[c]);
            p0[c] = fmaf(c0.y, gv.y, p0[c]);
            p0[c] = fmaf(c0.z, gv.z, p0[c]);
            p0[c] = fmaf(c0.w, gv.w, p0[c]);
            p1[c] = fmaf(c1.x, gv.x, p1[c]);
            p1[c] = fmaf(c1.y, gv.y, p1[c]);
            p1[c] = fmaf(c1.z, gv.z, p1[c]);
            p1[c] = fmaf(c1.w, gv.w, p1[c]);
        }
        jb = jn;
    }

    int slow = __syncthreads_or(viol);

    if (!slow) {
#pragma unroll
        for (int c = 0; c < C_OUT; c++) {
#pragma unroll
            for (int o = 16; o; o >>= 1) {
                p0[c] += __shfl_xor_sync(0xffffffffu, p0[c], o);
                p1[c] += __shfl_xor_sync(0xffffffffu, p1[c], o);
            }
        }
        if (lane == 0) {
#pragma unroll
            for (int c = 0; c < C_OUT; c++) {
                atomicAdd(&out[r0m * C_OUT + c], fmaf(A64, p0[c], B64 * sG[c]));
                atomicAdd(&out[r1m * C_OUT + c], fmaf(A64, p1[c], B64 * sG[c]));
            }
        }
    } else {
        // recompute tile with the fully general path (L2-hot re-read)
#pragma unroll
        for (int c = 0; c < C_OUT; c++) { p0[c] = 0.f; p1[c] = 0.f; }
        for (int j = lane * 4; j < JCHUNK; j += 128) {
            float4 c0 = *(const float4*)(d0p + j);
            float4 r0q = *(const float4*)(n0p + j);
            float4 c1 = *(const float4*)(d1p + j);
            float4 r1q = *(const float4*)(n1p + j);
            float dv[8], m[8];
            dv[0] = c0.x * frcp_nr(r0q.x); dv[1] = c0.y * frcp_nr(r0q.y);
            dv[2] = c0.z * frcp_nr(r0q.z); dv[3] = c0.w * frcp_nr(r0q.w);
            dv[4] = c1.x * frcp_nr(r1q.x); dv[5] = c1.y * frcp_nr(r1q.y);
            dv[6] = c1.z * frcp_nr(r1q.z); dv[7] = c1.w * frcp_nr(r1q.w);
#pragma unroll
            for (int t = 0; t < 8; t++) {
                float d = dv[t];
                int k = 0;
#pragma unroll
                for (int s = 32; s >= 1; s >>= 1)
                    if (__ldg(&g_bpG[k + s - 1]) < d) k += s;
                m[t] = fmaf(__ldg(&g_AG[k]), d, __ldg(&g_BG[k]));
            }
#pragma unroll
            for (int c = 0; c < C_OUT; c++) {
                float4 gv = *(const float4*)(gTs + c * JCHUNK + j);
                p0[c] = fmaf(m[0], gv.x, p0[c]);
                p0[c] = fmaf(m[1], gv.y, p0[c]);
                p0[c] = fmaf(m[2], gv.z, p0[c]);
                p0[c] = fmaf(m[3], gv.w, p0[c]);
                p1[c] = fmaf(m[4], gv.x, p1[c]);
                p1[c] = fmaf(m[5], gv.y, p1[c]);
                p1[c] = fmaf(m[6], gv.z, p1[c]);
                p1[c] = fmaf(m[7], gv.w, p1[c]);
            }
        }
#pragma unroll
        for (int c = 0; c < C_OUT; c++) {
#pragma unroll
            for (int o = 16; o; o >>= 1) {
                p0[c] += __shfl_xor_sync(0xffffffffu, p0[c], o);
                p1[c] += __shfl_xor_sync(0xffffffffu, p1[c], o);
            }
        }
        if (lane == 0) {
#pragma unroll
            for (int c = 0; c < C_OUT; c++) {
                atomicAdd(&out[r0m * C_OUT + c], p0[c]);
                atomicAdd(&out[r1m * C_OUT + c], p1[c]);
            }
        }
    }
}

// ---------------------------------------------------------------------------
extern "C" void kernel_launch(void* const* d_in, const int* in_sizes, int n_in,
                              void* d_out, int out_size) {
    const float* x   = (const float*)d_in[0];
    const float* nd  = (const float*)d_in[1];
    const float* nm  = (const float*)d_in[2];
    const float* W1  = (const float*)d_in[3];
    const float* b1  = (const float*)d_in[4];
    const float* W2  = (const float*)d_in[5];
    const float* b2  = (const float*)d_in[6];
    const float* Wm1 = (const float*)d_in[7];
    const float* bm1 = (const float*)d_in[8];
    const float* Wm2 = (const float*)d_in[9];
    const float* bm2 = (const float*)d_in[10];
    float* out = (float*)d_out;

    g_kernel<<<N_NODES / 16, 256>>>(x, W1, b1, W2, b2, Wm1, bm1, Wm2, bm2, out);

    dim3 mgrid(N_NODES / 16, NSPLIT);
    main_kernel<<<mgrid, 256>>>(nd, nm, out);
}